// round 7
// baseline (speedup 1.0000x reference)
#include <cuda_runtime.h>

#define Hh 512
#define Ww 512
#define HW (512*512)
#define NB 32
#define NSLOT (NB * Hh)   // one slot per block: 16384

// Per-block partials, written (not accumulated) each run -> no init pass needed.
__device__ float g_part[NSLOT];
__device__ unsigned int g_count;   // zero-initialized; reset by the last block each run

__global__ __launch_bounds__(128) void sym_main(const float* __restrict__ Flow,
                                                const float* __restrict__ Asym,
                                                const float* __restrict__ Bsym,
                                                const float* __restrict__ Mask,
                                                float* __restrict__ out)
{
    const int b = blockIdx.z;
    const int y = blockIdx.y;

    // Per-sample scalars (broadcast loads, L1/L2 hits)
    const float a0 = __ldg(Asym + 2 * b);
    const float a1 = __ldg(Asym + 2 * b + 1);
    const float b0 = __ldg(Bsym + 2 * b);
    const float b1 = __ldg(Bsym + 2 * b + 1);

    const float dxf = -3.0f * a0;
    const float dyf = fabsf(3.0f * a1);
    const float dy1 = floorf(dyf);
    const float dx1 = floorf(dxf);
    const float fy = dyf - dy1;
    const float fx = dxf - dx1;
    const int iy1 = (int)dy1;          // >= 0
    const int ix1 = (int)dx1;          // may be negative
    const int hp = Hh - 1 - iy1;
    const int x_lo = max(0, -ix1);
    const int x_hi = min(Ww, Ww - 1 - ix1);

    const float w11 = (1.f - fx) * (1.f - fy);
    const float w12 = fx * (1.f - fy);
    const float w21 = (1.f - fx) * fy;
    const float w22 = fx * fy;

    float acc = 0.f;

    if (y < hp && x_hi > x_lo) {
        const size_t boff = (size_t)b * 2 * HW;
        const float* f0 = Flow + boff;       // channel 0
        const float* f1 = f0 + HW;           // channel 1
        const float* m0 = Mask + boff;
        const float* m1 = m0 + HW;

        const int x4 = threadIdx.x * 4;
        const int idx = y * Ww + x4;
        const int g = (y + iy1) * Ww + x4 + ix1;

        if (x4 >= x_lo && x4 + 4 <= x_hi) {
            // Fast interior path: all 4 pixels valid, all indices provably in-bounds.
            float4 c0 = *reinterpret_cast<const float4*>(f0 + idx);
            float4 c1 = *reinterpret_cast<const float4*>(f1 + idx);
            float4 q0 = *reinterpret_cast<const float4*>(m0 + idx);
            float4 q1 = *reinterpret_cast<const float4*>(m1 + idx);

            // Four gather streams: 5-float misaligned windows (reuse s[i+1] as the
            // +1-column bilinear corner).
            float s10[5], s20[5], s11[5], s21[5];
            #pragma unroll
            for (int i = 0; i < 5; i++) {
                s10[i] = __ldg(f0 + g + i);
                s20[i] = __ldg(f0 + g + Ww + i);
                s11[i] = __ldg(f1 + g + i);
                s21[i] = __ldg(f1 + g + Ww + i);
            }

            const float cc0[4] = {c0.x, c0.y, c0.z, c0.w};
            const float cc1[4] = {c1.x, c1.y, c1.z, c1.w};
            const float mm[4]  = {q0.x + q1.x, q0.y + q1.y, q0.z + q1.z, q0.w + q1.w};

            #pragma unroll
            for (int i = 0; i < 4; i++) {
                float phi0 = w11 * s10[i] + w12 * s10[i + 1] + w21 * s20[i] + w22 * s20[i + 1];
                float phi1 = w11 * s11[i] + w12 * s11[i + 1] + w21 * s21[i] + w22 * s21[i + 1];
                float d0 = cc0[i] - phi0;
                float d1 = cc1[i] - phi1;
                float t = d1 * b0 - d0 * b1;
                acc += mm[i] * t * t;
            }
        } else {
            // Edge path: per-pixel predication; valid => in-bounds, no clamping needed.
            #pragma unroll
            for (int i = 0; i < 4; i++) {
                int x = x4 + i;
                if (x >= x_lo && x < x_hi) {
                    int id = y * Ww + x;
                    int gg = (y + iy1) * Ww + x + ix1;
                    float phi0 = w11 * f0[gg] + w12 * f0[gg + 1]
                               + w21 * f0[gg + Ww] + w22 * f0[gg + Ww + 1];
                    float phi1 = w11 * f1[gg] + w12 * f1[gg + 1]
                               + w21 * f1[gg + Ww] + w22 * f1[gg + Ww + 1];
                    float d0 = f0[id] - phi0;
                    float d1 = f1[id] - phi1;
                    float t = d1 * b0 - d0 * b1;
                    acc += (m0[id] + m1[id]) * t * t;
                }
            }
        }
    }

    // Block reduction: warp shuffle then shared.
    #pragma unroll
    for (int o = 16; o > 0; o >>= 1)
        acc += __shfl_xor_sync(0xffffffffu, acc, o);

    __shared__ float ws[4];
    __shared__ int is_last;
    const int tid = threadIdx.x;
    const int wid = tid >> 5;
    if ((tid & 31) == 0) ws[wid] = acc;
    __syncthreads();

    if (tid == 0) {
        float s = ws[0] + ws[1] + ws[2] + ws[3];
        float hpf = (float)max(hp, 1);
        float wf  = (float)max(x_hi - x_lo, 1);
        // Pre-scale by this sample's denom and the batch mean; plain store, no atomic.
        double denom = 2.0 * (double)hpf * (double)wf * (double)NB;
        g_part[b * Hh + y] = (float)((double)s / denom);
        __threadfence();
        unsigned int arrived = atomicAdd(&g_count, 1u);
        is_last = (arrived == NSLOT - 1) ? 1 : 0;
    }
    __syncthreads();

    // Last block to finish reduces all partials (L2-hot) and writes the output.
    if (is_last) {
        double s = 0.0;
        const float4* p = reinterpret_cast<const float4*>(g_part);
        // 16384 floats = 4096 float4; 128 threads x 32 each.
        #pragma unroll
        for (int i = 0; i < 32; i++) {
            float4 v = p[tid + i * 128];
            s += (double)v.x + (double)v.y + (double)v.z + (double)v.w;
        }
        #pragma unroll
        for (int o = 16; o > 0; o >>= 1)
            s += __shfl_xor_sync(0xffffffffu, s, o);

        __shared__ double wsum[4];
        if ((tid & 31) == 0) wsum[wid] = s;
        __syncthreads();
        if (tid == 0) {
            out[0] = (float)(wsum[0] + wsum[1] + wsum[2] + wsum[3]);
            g_count = 0;   // reset for the next graph replay
        }
    }
}

extern "C" void kernel_launch(void* const* d_in, const int* in_sizes, int n_in,
                              void* d_out, int out_size)
{
    const float* Flow = (const float*)d_in[0];
    const float* A    = (const float*)d_in[1];
    const float* Bs   = (const float*)d_in[2];
    const float* Mask = (const float*)d_in[3];

    dim3 grid(1, Hh, NB);
    sym_main<<<grid, 128>>>(Flow, A, Bs, Mask, (float*)d_out);
}

// round 10
// speedup vs baseline: 1.3550x; 1.3550x over previous
#include <cuda_runtime.h>

#define Hh 512
#define Ww 512
#define HW (512*512)
#define NB 32
#define TROWS 4
#define NTY (Hh / TROWS)          // 128 row-tiles
#define NSLOT (NB * NTY)          // 4096 per-block partials

// Per-block partials, written (not accumulated) each run -> no init pass needed.
__device__ float g_part[NSLOT];

__global__ __launch_bounds__(128) void sym_main(const float* __restrict__ Flow,
                                                const float* __restrict__ Asym,
                                                const float* __restrict__ Bsym,
                                                const float* __restrict__ Mask)
{
    const int b  = blockIdx.z;
    const int y0 = blockIdx.y * TROWS;

    const float a0 = __ldg(Asym + 2 * b);
    const float a1 = __ldg(Asym + 2 * b + 1);
    const float b0 = __ldg(Bsym + 2 * b);
    const float b1 = __ldg(Bsym + 2 * b + 1);

    const float dxf = -3.0f * a0;
    const float dyf = fabsf(3.0f * a1);
    const float dy1 = floorf(dyf);
    const float dx1 = floorf(dxf);
    const float fy = dyf - dy1;
    const float fx = dxf - dx1;
    const int iy1 = (int)dy1;          // >= 0
    const int ix1 = (int)dx1;          // may be negative
    const int hp = Hh - 1 - iy1;
    const int x_lo = max(0, -ix1);
    const int x_hi = min(Ww, Ww - 1 - ix1);

    const float w11 = (1.f - fx) * (1.f - fy);
    const float w12 = fx * (1.f - fy);
    const float w21 = (1.f - fx) * fy;
    const float w22 = fx * fy;

    float acc = 0.f;

    if (y0 < hp && x_hi > x_lo) {
        const int nrows = min(TROWS, hp - y0);
        const size_t boff = (size_t)b * 2 * HW;
        const float* f0 = Flow + boff;
        const float* f1 = f0 + HW;
        const float* m0 = Mask + boff;
        const float* m1 = m0 + HW;

        const int x4 = threadIdx.x * 4;

        if (x4 >= x_lo && x4 + 4 <= x_hi) {
            // Fast path: rolling 5-float gather windows shared across consecutive rows.
            // Row y uses gather rows y+iy1 (top) and y+iy1+1 (bot); bot becomes next
            // row's top, so 4 center rows need only 5 gather-row loads per channel.
            const int g0 = (y0 + iy1) * Ww + x4 + ix1;

            float t0[5], u0[5], t1[5], u1[5];   // ch0 top/bot, ch1 top/bot
            #pragma unroll
            for (int i = 0; i < 5; i++) {
                t0[i] = __ldg(f0 + g0 + i);
                t1[i] = __ldg(f1 + g0 + i);
                u0[i] = __ldg(f0 + g0 + Ww + i);
                u1[i] = __ldg(f1 + g0 + Ww + i);
            }

            #pragma unroll
            for (int r = 0; r < TROWS; r++) {
                if (r < nrows) {
                    const int idx = (y0 + r) * Ww + x4;
                    float4 c0 = *reinterpret_cast<const float4*>(f0 + idx);
                    float4 c1 = *reinterpret_cast<const float4*>(f1 + idx);
                    float4 q0 = *reinterpret_cast<const float4*>(m0 + idx);
                    float4 q1 = *reinterpret_cast<const float4*>(m1 + idx);

                    const float cc0[4] = {c0.x, c0.y, c0.z, c0.w};
                    const float cc1[4] = {c1.x, c1.y, c1.z, c1.w};
                    const float mm[4]  = {q0.x + q1.x, q0.y + q1.y, q0.z + q1.z, q0.w + q1.w};

                    #pragma unroll
                    for (int i = 0; i < 4; i++) {
                        float phi0 = w11 * t0[i] + w12 * t0[i + 1] + w21 * u0[i] + w22 * u0[i + 1];
                        float phi1 = w11 * t1[i] + w12 * t1[i + 1] + w21 * u1[i] + w22 * u1[i + 1];
                        float d0 = cc0[i] - phi0;
                        float d1 = cc1[i] - phi1;
                        float t = d1 * b0 - d0 * b1;
                        acc += mm[i] * t * t;
                    }
                }
                if (r < TROWS - 1 && r + 1 < nrows) {
                    // Roll: bot -> top, load new bot row (y0+r+1+iy1+1).
                    const int gn = g0 + (r + 2) * Ww;
                    #pragma unroll
                    for (int i = 0; i < 5; i++) {
                        t0[i] = u0[i];
                        t1[i] = u1[i];
                        u0[i] = __ldg(f0 + gn + i);
                        u1[i] = __ldg(f1 + gn + i);
                    }
                }
            }
        } else {
            // Edge path: per-pixel predication; valid => in-bounds, no clamping needed.
            for (int r = 0; r < nrows; r++) {
                const int y = y0 + r;
                #pragma unroll
                for (int i = 0; i < 4; i++) {
                    int x = x4 + i;
                    if (x >= x_lo && x < x_hi) {
                        int id = y * Ww + x;
                        int gg = (y + iy1) * Ww + x + ix1;
                        float phi0 = w11 * f0[gg] + w12 * f0[gg + 1]
                                   + w21 * f0[gg + Ww] + w22 * f0[gg + Ww + 1];
                        float phi1 = w11 * f1[gg] + w12 * f1[gg + 1]
                                   + w21 * f1[gg + Ww] + w22 * f1[gg + Ww + 1];
                        float d0 = f0[id] - phi0;
                        float d1 = f1[id] - phi1;
                        float t = d1 * b0 - d0 * b1;
                        acc += (m0[id] + m1[id]) * t * t;
                    }
                }
            }
        }
    }

    // Block reduction: warp shuffle then shared.
    #pragma unroll
    for (int o = 16; o > 0; o >>= 1)
        acc += __shfl_xor_sync(0xffffffffu, acc, o);

    __shared__ float ws[4];
    const int tid = threadIdx.x;
    if ((tid & 31) == 0) ws[tid >> 5] = acc;
    __syncthreads();

    if (tid == 0) {
        float s = ws[0] + ws[1] + ws[2] + ws[3];
        float hpf = (float)max(hp, 1);
        float wf  = (float)max(x_hi - x_lo, 1);
        // Pre-scale by this sample's denom and the batch mean; plain store, no atomic.
        double denom = 2.0 * (double)hpf * (double)wf * (double)NB;
        g_part[b * NTY + blockIdx.y] = (float)((double)s / denom);
    }
}

// Single-block reduction of 4096 floats (16KB, L2-hot) in fp64.
__global__ __launch_bounds__(256) void fin_k(float* out) {
    const int tid = threadIdx.x;
    double s = 0.0;
    const float4* p = reinterpret_cast<const float4*>(g_part);
    // 4096 floats = 1024 float4; 256 threads x 4 each.
    #pragma unroll
    for (int i = 0; i < 4; i++) {
        float4 v = p[tid + i * 256];
        s += (double)v.x + (double)v.y + (double)v.z + (double)v.w;
    }
    #pragma unroll
    for (int o = 16; o > 0; o >>= 1)
        s += __shfl_xor_sync(0xffffffffu, s, o);

    __shared__ double wsum[8];
    if ((tid & 31) == 0) wsum[tid >> 5] = s;
    __syncthreads();
    if (tid == 0) {
        double t = 0.0;
        #pragma unroll
        for (int i = 0; i < 8; i++) t += wsum[i];
        out[0] = (float)t;
    }
}

extern "C" void kernel_launch(void* const* d_in, const int* in_sizes, int n_in,
                              void* d_out, int out_size)
{
    const float* Flow = (const float*)d_in[0];
    const float* A    = (const float*)d_in[1];
    const float* Bs   = (const float*)d_in[2];
    const float* Mask = (const float*)d_in[3];

    dim3 grid(1, NTY, NB);
    sym_main<<<grid, 128>>>(Flow, A, Bs, Mask);
    fin_k<<<1, 256>>>((float*)d_out);
}